// round 4
// baseline (speedup 1.0000x reference)
#include <cuda_runtime.h>
#include <math.h>

#define IMG_W 512
#define IMG_H 512

// AAN (Arai-Agui-Nakajima) 8-point forward DCT, libjpeg jfdctflt flowgraph.
// Output k must later be divided by (8 * asf[k]) per dimension, where
// asf[0]=1, asf[k]=cos(k*pi/16)*sqrt(2) — folded into the quant table.
__device__ __forceinline__ void aan_dct8(float* d)
{
    float tmp0 = d[0] + d[7], tmp7 = d[0] - d[7];
    float tmp1 = d[1] + d[6], tmp6 = d[1] - d[6];
    float tmp2 = d[2] + d[5], tmp5 = d[2] - d[5];
    float tmp3 = d[3] + d[4], tmp4 = d[3] - d[4];

    float tmp10 = tmp0 + tmp3, tmp13 = tmp0 - tmp3;
    float tmp11 = tmp1 + tmp2, tmp12 = tmp1 - tmp2;

    d[0] = tmp10 + tmp11;
    d[4] = tmp10 - tmp11;

    float z1 = (tmp12 + tmp13) * 0.707106781f;
    d[2] = tmp13 + z1;
    d[6] = tmp13 - z1;

    tmp10 = tmp4 + tmp5;
    tmp11 = tmp5 + tmp6;
    tmp12 = tmp6 + tmp7;

    float z5 = (tmp10 - tmp12) * 0.382683433f;
    float z2 = fmaf(0.541196100f, tmp10, z5);
    float z4 = fmaf(1.306562965f, tmp12, z5);
    float z3 = tmp11 * 0.707106781f;

    float z11 = tmp7 + z3;
    float z13 = tmp7 - z3;

    d[5] = z13 + z2;
    d[3] = z13 - z2;
    d[1] = z11 + z4;
    d[7] = z11 - z4;
}

// One CTA handles a 64(W) x 16(H) pixel tile of one image.
//   -> 16 Y 8x8 blocks (2 rows x 8 cols)
//   ->  4 Cb + 4 Cr 8x8 blocks (pooled 32x8 region)
__global__ void __launch_bounds__(256)
jpeg_compress_kernel(const float* __restrict__ img, float* __restrict__ out)
{
    __shared__ float sY  [16][68];   // Y - 128, padded for conflict-free float4
    __shared__ float sCbP[8][36];    // pooled Cb (centered)
    __shared__ float sCrP[8][36];    // pooled Cr (centered)
    __shared__ float sQ  [128];      // [0:64) Y, [64:128) C: 1/(8*asf_u*asf_v*q)

    const int t       = threadIdx.x;
    const int tileCol = blockIdx.x;   // 0..7
    const int tileRow = blockIdx.y;   // 0..31
    const int b       = blockIdx.z;
    const int nbatch  = gridDim.z;

    // --- quant coefficient tables with AAN scale folded in (double precision) ---
    if (t < 64) {
        constexpr int YT[64] = {
            16,11,10,16,24,40,51,61, 12,12,14,19,26,58,60,55,
            14,13,16,24,40,57,69,56, 14,17,22,29,51,87,80,62,
            18,22,37,56,68,109,103,77, 24,35,55,64,81,104,113,92,
            49,64,78,87,103,121,120,101, 72,92,95,98,112,100,103,99};
        constexpr int CT[64] = {
            17,18,24,47,99,99,99,99, 18,21,26,66,99,99,99,99,
            24,26,56,99,99,99,99,99, 47,66,99,99,99,99,99,99,
            99,99,99,99,99,99,99,99, 99,99,99,99,99,99,99,99,
            99,99,99,99,99,99,99,99, 99,99,99,99,99,99,99,99};
        int uu = t >> 3, vv = t & 7;
        double asfu = uu ? cos(uu * M_PI / 16.0) * 1.41421356237309504880 : 1.0;
        double asfv = vv ? cos(vv * M_PI / 16.0) * 1.41421356237309504880 : 1.0;
        double sc = 1.0 / (8.0 * asfu * asfv);
        sQ[t]      = (float)(sc / (double)YT[t]);
        sQ[64 + t] = (float)(sc / (double)CT[t]);
    }

    // --- Phase 1: coalesced float4 loads, RGB -> YCbCr, register chroma pooling ---
    const size_t plane = (size_t)IMG_H * IMG_W;
    const float* base = img + (size_t)b * 3 * plane
                      + (size_t)(tileRow * 16) * IMG_W + tileCol * 64;
    {
        const int r  = t >> 4;          // 0..15
        const int c4 = (t & 15) * 4;
        const float4 R4 = *reinterpret_cast<const float4*>(base + (size_t)r * IMG_W + c4);
        const float4 G4 = *reinterpret_cast<const float4*>(base + plane + (size_t)r * IMG_W + c4);
        const float4 B4 = *reinterpret_cast<const float4*>(base + 2 * plane + (size_t)r * IMG_W + c4);
        float Rv[4] = {R4.x, R4.y, R4.z, R4.w};
        float Gv[4] = {G4.x, G4.y, G4.z, G4.w};
        float Bv[4] = {B4.x, B4.y, B4.z, B4.w};
        float y[4], cb[4], cr[4];
        #pragma unroll
        for (int i = 0; i < 4; i++) {
            float R = Rv[i] * 255.0f;
            float G = Gv[i] * 255.0f;
            float B = Bv[i] * 255.0f;
            y [i] =  0.299f    * R + 0.587f    * G + 0.114f    * B - 128.0f;
            cb[i] = -0.168736f * R - 0.331264f * G + 0.5f      * B;
            cr[i] =  0.5f      * R - 0.418688f * G - 0.081312f * B;
        }
        *reinterpret_cast<float4*>(&sY[r][c4]) = make_float4(y[0], y[1], y[2], y[3]);

        // horizontal pool in registers, vertical pool via shfl with partner row (lane ^ 16)
        float hcb0 = cb[0] + cb[1], hcb1 = cb[2] + cb[3];
        float hcr0 = cr[0] + cr[1], hcr1 = cr[2] + cr[3];
        float pcb0 = hcb0 + __shfl_xor_sync(0xffffffffu, hcb0, 16);
        float pcb1 = hcb1 + __shfl_xor_sync(0xffffffffu, hcb1, 16);
        float pcr0 = hcr0 + __shfl_xor_sync(0xffffffffu, hcr0, 16);
        float pcr1 = hcr1 + __shfl_xor_sync(0xffffffffu, hcr1, 16);
        if (!(t & 16)) {
            int pr = r >> 1;
            int pc = (t & 15) * 2;
            *reinterpret_cast<float2*>(&sCbP[pr][pc]) = make_float2(0.25f * pcb0, 0.25f * pcb1);
            *reinterpret_cast<float2*>(&sCrP[pr][pc]) = make_float2(0.25f * pcr0, 0.25f * pcr1);
        }
    }
    __syncthreads();

    // --- Phase 3: 24 blocks x 8 threads, register AAN DCT + shfl transpose ---
    const int blk = t >> 3;   // 0..31 (24 active)
    const int x   = t & 7;

    if (blk < 24) {
        float d[8];
        if (blk < 16) {
            int by = blk >> 3, bx = blk & 7;
            float4 a = *reinterpret_cast<const float4*>(&sY[by * 8 + x][bx * 8]);
            float4 c = *reinterpret_cast<const float4*>(&sY[by * 8 + x][bx * 8 + 4]);
            d[0]=a.x; d[1]=a.y; d[2]=a.z; d[3]=a.w;
            d[4]=c.x; d[5]=c.y; d[6]=c.z; d[7]=c.w;
        } else {
            const float (*src)[36] = (blk < 20) ? sCbP : sCrP;
            int bx = (blk < 20) ? (blk - 16) : (blk - 20);
            float4 a = *reinterpret_cast<const float4*>(&src[x][bx * 8]);
            float4 c = *reinterpret_cast<const float4*>(&src[x][bx * 8 + 4]);
            d[0]=a.x; d[1]=a.y; d[2]=a.z; d[3]=a.w;
            d[4]=c.x; d[5]=c.y; d[6]=c.z; d[7]=c.w;
        }

        // Pass A: row DCT (lane x owns spatial row x; d[v] = freq v)
        aan_dct8(d);

        // In-register 8x8 transpose across the 8-lane group:
        // after this, lane v holds t1[x][v] in d[x].
        #pragma unroll
        for (int m = 1; m < 8; m <<= 1) {
            #pragma unroll
            for (int j0 = 0; j0 < 8; j0++) {
                if (j0 & m) continue;
                int j1 = j0 | m;
                float a   = (x & m) ? d[j0] : d[j1];
                float bsh = __shfl_xor_sync(0xffffffffu, a, m);
                if (x & m) d[j0] = bsh; else d[j1] = bsh;
            }
        }

        // Pass B: column DCT (lane v owns column v; d[u] = 2-D AAN coeff (u,v))
        aan_dct8(d);

        // Output offset for this block; this lane owns output column v = x
        const int v = x;
        size_t off;
        int qbase;
        if (blk < 16) {
            int by = blk >> 3, bx = blk & 7;
            int n = (tileRow * 2 + by) * 64 + (tileCol * 8 + bx);
            off = (size_t)b * 4096 * 64 + (size_t)n * 64;
            qbase = 0;
        } else {
            size_t cbBase = (size_t)nbatch * 4096 * 64;
            int bx, comp;
            if (blk < 20) { bx = blk - 16; comp = 0; }
            else          { bx = blk - 20; comp = 1; }
            int n = tileRow * 32 + tileCol * 4 + bx;
            off = cbBase + (size_t)comp * nbatch * 1024 * 64
                + (size_t)b * 1024 * 64 + (size_t)n * 64;
            qbase = 64;
        }

        // Quantize (AAN scale folded into sQ) + round-half-even + store
        float* dst = out + off + v;
        #pragma unroll
        for (int u = 0; u < 8; u++)
            dst[u * 8] = rintf(d[u] * sQ[qbase + u * 8 + v]);
    }
}

extern "C" void kernel_launch(void* const* d_in, const int* in_sizes, int n_in,
                              void* d_out, int out_size)
{
    const float* img = (const float*)d_in[0];
    float* out = (float*)d_out;
    int nbatch = in_sizes[0] / (3 * IMG_H * IMG_W);
    dim3 grid(IMG_W / 64, IMG_H / 16, nbatch);
    jpeg_compress_kernel<<<grid, 256>>>(img, out);
}

// round 5
// speedup vs baseline: 2.5626x; 2.5626x over previous
#include <cuda_runtime.h>
#include <math.h>

#define IMG_W 512
#define IMG_H 512

// AAN (Arai-Agui-Nakajima) 8-point forward DCT, libjpeg jfdctflt flowgraph.
// Output k must later be divided by (8 * asf[k]) per dimension, where
// asf[0]=1, asf[k]=cos(k*pi/16)*sqrt(2) — folded into the quant table.
__device__ __forceinline__ void aan_dct8(float* d)
{
    float tmp0 = d[0] + d[7], tmp7 = d[0] - d[7];
    float tmp1 = d[1] + d[6], tmp6 = d[1] - d[6];
    float tmp2 = d[2] + d[5], tmp5 = d[2] - d[5];
    float tmp3 = d[3] + d[4], tmp4 = d[3] - d[4];

    float tmp10 = tmp0 + tmp3, tmp13 = tmp0 - tmp3;
    float tmp11 = tmp1 + tmp2, tmp12 = tmp1 - tmp2;

    d[0] = tmp10 + tmp11;
    d[4] = tmp10 - tmp11;

    float z1 = (tmp12 + tmp13) * 0.707106781f;
    d[2] = tmp13 + z1;
    d[6] = tmp13 - z1;

    tmp10 = tmp4 + tmp5;
    tmp11 = tmp5 + tmp6;
    tmp12 = tmp6 + tmp7;

    float z5 = (tmp10 - tmp12) * 0.382683433f;
    float z2 = fmaf(0.541196100f, tmp10, z5);
    float z4 = fmaf(1.306562965f, tmp12, z5);
    float z3 = tmp11 * 0.707106781f;

    float z11 = tmp7 + z3;
    float z13 = tmp7 - z3;

    d[5] = z13 + z2;
    d[3] = z13 - z2;
    d[1] = z11 + z4;
    d[7] = z11 - z4;
}

// Quantization divisors 1/(8*asf_u*asf_v*q) — all fp32, no FP64 anywhere.
__constant__ int c_yt[64] = {
    16,11,10,16,24,40,51,61, 12,12,14,19,26,58,60,55,
    14,13,16,24,40,57,69,56, 14,17,22,29,51,87,80,62,
    18,22,37,56,68,109,103,77, 24,35,55,64,81,104,113,92,
    49,64,78,87,103,121,120,101, 72,92,95,98,112,100,103,99};
__constant__ int c_ct[64] = {
    17,18,24,47,99,99,99,99, 18,21,26,66,99,99,99,99,
    24,26,56,99,99,99,99,99, 47,66,99,99,99,99,99,99,
    99,99,99,99,99,99,99,99, 99,99,99,99,99,99,99,99,
    99,99,99,99,99,99,99,99, 99,99,99,99,99,99,99,99};
__constant__ float c_asf[8] = {
    1.0f, 1.3870398453f, 1.3065629649f, 1.1758756024f,
    1.0f, 0.7856949583f, 0.5411961001f, 0.2758993792f};

// One CTA handles a 64(W) x 16(H) pixel tile of one image.
//   -> 16 Y 8x8 blocks (2 rows x 8 cols)
//   ->  4 Cb + 4 Cr 8x8 blocks (pooled 32x8 region)
__global__ void __launch_bounds__(256)
jpeg_compress_kernel(const float* __restrict__ img, float* __restrict__ out)
{
    __shared__ float sY  [16][68];   // Y - 128, padded for conflict-free float4
    __shared__ float sCbP[8][36];    // pooled Cb (centered)
    __shared__ float sCrP[8][36];    // pooled Cr (centered)
    __shared__ float sQ  [128];      // [0:64) Y, [64:128) C

    const int t       = threadIdx.x;
    const int tileCol = blockIdx.x;   // 0..7
    const int tileRow = blockIdx.y;   // 0..31
    const int b       = blockIdx.z;
    const int nbatch  = gridDim.z;

    // --- quant coefficient tables (pure fp32) ---
    if (t < 64) {
        int uu = t >> 3, vv = t & 7;
        float sc = 1.0f / (8.0f * c_asf[uu] * c_asf[vv]);
        sQ[t]      = sc / (float)c_yt[t];
        sQ[64 + t] = sc / (float)c_ct[t];
    }

    // --- Phase 1: coalesced float4 loads, RGB -> YCbCr, register chroma pooling ---
    const size_t plane = (size_t)IMG_H * IMG_W;
    const float* base = img + (size_t)b * 3 * plane
                      + (size_t)(tileRow * 16) * IMG_W + tileCol * 64;
    {
        const int r  = t >> 4;          // 0..15
        const int c4 = (t & 15) * 4;
        const float4 R4 = *reinterpret_cast<const float4*>(base + (size_t)r * IMG_W + c4);
        const float4 G4 = *reinterpret_cast<const float4*>(base + plane + (size_t)r * IMG_W + c4);
        const float4 B4 = *reinterpret_cast<const float4*>(base + 2 * plane + (size_t)r * IMG_W + c4);
        float Rv[4] = {R4.x, R4.y, R4.z, R4.w};
        float Gv[4] = {G4.x, G4.y, G4.z, G4.w};
        float Bv[4] = {B4.x, B4.y, B4.z, B4.w};
        float y[4], cb[4], cr[4];
        #pragma unroll
        for (int i = 0; i < 4; i++) {
            float R = Rv[i] * 255.0f;
            float G = Gv[i] * 255.0f;
            float B = Bv[i] * 255.0f;
            y [i] =  0.299f    * R + 0.587f    * G + 0.114f    * B - 128.0f;
            cb[i] = -0.168736f * R - 0.331264f * G + 0.5f      * B;
            cr[i] =  0.5f      * R - 0.418688f * G - 0.081312f * B;
        }
        *reinterpret_cast<float4*>(&sY[r][c4]) = make_float4(y[0], y[1], y[2], y[3]);

        // horizontal pool in registers, vertical pool via shfl with partner row (lane ^ 16)
        float hcb0 = cb[0] + cb[1], hcb1 = cb[2] + cb[3];
        float hcr0 = cr[0] + cr[1], hcr1 = cr[2] + cr[3];
        float pcb0 = hcb0 + __shfl_xor_sync(0xffffffffu, hcb0, 16);
        float pcb1 = hcb1 + __shfl_xor_sync(0xffffffffu, hcb1, 16);
        float pcr0 = hcr0 + __shfl_xor_sync(0xffffffffu, hcr0, 16);
        float pcr1 = hcr1 + __shfl_xor_sync(0xffffffffu, hcr1, 16);
        if (!(t & 16)) {
            int pr = r >> 1;
            int pc = (t & 15) * 2;
            *reinterpret_cast<float2*>(&sCbP[pr][pc]) = make_float2(0.25f * pcb0, 0.25f * pcb1);
            *reinterpret_cast<float2*>(&sCrP[pr][pc]) = make_float2(0.25f * pcr0, 0.25f * pcr1);
        }
    }
    __syncthreads();

    // --- Phase 3: 24 blocks x 8 threads, register AAN DCT + shfl transpose ---
    const int blk = t >> 3;   // 0..31 (24 active)
    const int x   = t & 7;

    if (blk < 24) {
        float d[8];
        if (blk < 16) {
            int by = blk >> 3, bx = blk & 7;
            float4 a = *reinterpret_cast<const float4*>(&sY[by * 8 + x][bx * 8]);
            float4 c = *reinterpret_cast<const float4*>(&sY[by * 8 + x][bx * 8 + 4]);
            d[0]=a.x; d[1]=a.y; d[2]=a.z; d[3]=a.w;
            d[4]=c.x; d[5]=c.y; d[6]=c.z; d[7]=c.w;
        } else {
            const float (*src)[36] = (blk < 20) ? sCbP : sCrP;
            int bx = (blk < 20) ? (blk - 16) : (blk - 20);
            float4 a = *reinterpret_cast<const float4*>(&src[x][bx * 8]);
            float4 c = *reinterpret_cast<const float4*>(&src[x][bx * 8 + 4]);
            d[0]=a.x; d[1]=a.y; d[2]=a.z; d[3]=a.w;
            d[4]=c.x; d[5]=c.y; d[6]=c.z; d[7]=c.w;
        }

        // Pass A: row DCT (lane x owns spatial row x; d[v] = freq v)
        aan_dct8(d);

        // In-register 8x8 transpose across the 8-lane group:
        // after this, lane v holds t1[x][v] in d[x].
        #pragma unroll
        for (int m = 1; m < 8; m <<= 1) {
            #pragma unroll
            for (int j0 = 0; j0 < 8; j0++) {
                if (j0 & m) continue;
                int j1 = j0 | m;
                float a   = (x & m) ? d[j0] : d[j1];
                float bsh = __shfl_xor_sync(0xffffffffu, a, m);
                if (x & m) d[j0] = bsh; else d[j1] = bsh;
            }
        }

        // Pass B: column DCT (lane v owns column v; d[u] = 2-D AAN coeff (u,v))
        aan_dct8(d);

        // Output offset for this block; this lane owns output column v = x
        const int v = x;
        size_t off;
        int qbase;
        if (blk < 16) {
            int by = blk >> 3, bx = blk & 7;
            int n = (tileRow * 2 + by) * 64 + (tileCol * 8 + bx);
            off = (size_t)b * 4096 * 64 + (size_t)n * 64;
            qbase = 0;
        } else {
            size_t cbBase = (size_t)nbatch * 4096 * 64;
            int bx, comp;
            if (blk < 20) { bx = blk - 16; comp = 0; }
            else          { bx = blk - 20; comp = 1; }
            int n = tileRow * 32 + tileCol * 4 + bx;
            off = cbBase + (size_t)comp * nbatch * 1024 * 64
                + (size_t)b * 1024 * 64 + (size_t)n * 64;
            qbase = 64;
        }

        // Quantize (AAN scale folded into sQ) + round-half-even + store
        float* dst = out + off + v;
        #pragma unroll
        for (int u = 0; u < 8; u++)
            dst[u * 8] = rintf(d[u] * sQ[qbase + u * 8 + v]);
    }
}

extern "C" void kernel_launch(void* const* d_in, const int* in_sizes, int n_in,
                              void* d_out, int out_size)
{
    const float* img = (const float*)d_in[0];
    float* out = (float*)d_out;
    int nbatch = in_sizes[0] / (3 * IMG_H * IMG_W);
    dim3 grid(IMG_W / 64, IMG_H / 16, nbatch);
    jpeg_compress_kernel<<<grid, 256>>>(img, out);
}